// round 6
// baseline (speedup 1.0000x reference)
#include <cuda_runtime.h>
#include <math.h>

#define N      4096
#define D      128
#define NW     128          // 4096 bits / 32
#define MLP_R  16           // rows per MLP block
#define WCAP   320          // per-warp neighbor list capacity
#define XSTRIDE 36          // dup-x smem row stride (floats)
#define INV232 2.3283064365386963e-10f   // 2^-32

// ---------------- scratch (device globals) ----------------------------------
__device__ unsigned  g_A  [N * NW];
__device__ unsigned  g_A2 [N * NW];
__device__ float     g_Wt [3 * D * D];   // pre-transposed weights, k-major
__device__ float     g_a0[N];
__device__ float     g_av2[N];
__device__ long long g_stepq[N];
__device__ float     g_step[N];
__device__ int       g_is64;

#define FMA2(acc, w, x) asm("fma.rn.f32x2 %0, %1, %2, %0;" : "+l"(acc) : "l"(w), "l"(x))
union U64F2 { unsigned long long u; float2 f; };

__device__ __forceinline__ int popc4(uint4 v) {
    return __popc(v.x) + __popc(v.y) + __popc(v.z) + __popc(v.w);
}

// ---------------- prep: zero A/stepq + transpose W0..W2 + dtype detect ------
__global__ void prep_kernel(const float* __restrict__ W0,
                            const float* __restrict__ W1,
                            const float* __restrict__ W2,
                            const void* __restrict__ ei) {
    if (blockIdx.x == gridDim.x - 1) {
        __shared__ int bad;
        if (threadIdx.x == 0) bad = 0;
        __syncthreads();
        const long long* p = (const long long*)ei;
        for (int i = threadIdx.x; i < 2048; i += blockDim.x) {
            long long v = p[i];
            if (v < 0 || v >= N) bad = 1;
        }
        __syncthreads();
        if (threadIdx.x == 0) g_is64 = bad ? 0 : 1;
        return;
    }
    int idx = blockIdx.x * 256 + threadIdx.x;
    if (idx < N * NW) {
        g_A[idx] = 0u;
        if (idx < N) g_stepq[idx] = 0ll;
    } else {
        int t = idx - N * NW;
        int m  = t >> 14;
        int tp = t & 16383;                  // tp = k*128 + c
        int c  = tp & 127;
        int k  = tp >> 7;
        const float* Ws = (m == 0) ? W0 : (m == 1 ? W1 : W2);
        g_Wt[m * 16384 + tp] = Ws[c * 128 + k];
    }
}

// ---------------- fused MLP: 3 x (GEMM+ReLU) + final dot, one kernel --------
__global__ __launch_bounds__(128, 4)
void mlp_kernel(const float* __restrict__ coeffs,
                const float* __restrict__ b0,
                const float* __restrict__ W3,
                const float* __restrict__ b3) {
    __shared__ float xa[128 * XSTRIDE];
    __shared__ float xb[128 * XSTRIDE];

    const int tid = threadIdx.x;
    const int r0  = blockIdx.x * MLP_R;
    const int rg  = tid >> 4;     // 8 row-groups of 2 rows
    const int cg  = tid & 15;     // 16 col-groups

    #pragma unroll
    for (int it = 0; it < 4; it++) {
        int idx = it * 128 + tid;
        int r  = idx >> 5;
        int kq = idx & 31;
        float4 v = *(const float4*)&coeffs[(r0 + r) * 128 + kq * 4];
        float vv[4] = {v.x, v.y, v.z, v.w};
        #pragma unroll
        for (int q = 0; q < 4; q++)
            *(float2*)&xa[(kq * 4 + q) * XSTRIDE + 2 * r] = make_float2(vv[q], vv[q]);
    }
    __syncthreads();

    float* Xin  = xa;
    float* Xout = xb;

    #pragma unroll
    for (int layer = 0; layer < 3; layer++) {
        const float* Wl = g_Wt + layer * 16384;

        unsigned long long a0p[4], a1p[4];
        #pragma unroll
        for (int j = 0; j < 4; j++) { a0p[j] = 0ull; a1p[j] = 0ull; }

        #pragma unroll 8
        for (int k = 0; k < 128; k++) {
            ulonglong2 xx = *(const ulonglong2*)&Xin[k * XSTRIDE + rg * 4];
            const float* wrow = Wl + k * 128 + cg * 2;
            unsigned long long w0 = *(const unsigned long long*)(wrow);
            unsigned long long w1 = *(const unsigned long long*)(wrow + 32);
            unsigned long long w2 = *(const unsigned long long*)(wrow + 64);
            unsigned long long w3 = *(const unsigned long long*)(wrow + 96);
            FMA2(a0p[0], w0, xx.x); FMA2(a1p[0], w0, xx.y);
            FMA2(a0p[1], w1, xx.x); FMA2(a1p[1], w1, xx.y);
            FMA2(a0p[2], w2, xx.x); FMA2(a1p[2], w2, xx.y);
            FMA2(a0p[3], w3, xx.x); FMA2(a1p[3], w3, xx.y);
        }

        float o0[8], o1[8];
        #pragma unroll
        for (int j = 0; j < 4; j++) {
            U64F2 u0, u1; u0.u = a0p[j]; u1.u = a1p[j];
            o0[2 * j] = u0.f.x; o0[2 * j + 1] = u0.f.y;
            o1[2 * j] = u1.f.x; o1[2 * j + 1] = u1.f.y;
        }
        if (layer == 0) {
            #pragma unroll
            for (int j = 0; j < 4; j++) {
                float2 bb = *(const float2*)&b0[32 * j + cg * 2];
                o0[2 * j] += bb.x; o0[2 * j + 1] += bb.y;
                o1[2 * j] += bb.x; o1[2 * j + 1] += bb.y;
            }
        }
        #pragma unroll
        for (int j = 0; j < 8; j++) {
            o0[j] = fmaxf(o0[j], 0.f);
            o1[j] = fmaxf(o1[j], 0.f);
        }

        if (layer < 2) {
            #pragma unroll
            for (int j = 0; j < 4; j++) {
                int k0 = cg * 2 + 32 * j;
                *(float2*)&Xout[(k0    ) * XSTRIDE + 4 * rg    ] = make_float2(o0[2*j],   o0[2*j]);
                *(float2*)&Xout[(k0 + 1) * XSTRIDE + 4 * rg    ] = make_float2(o0[2*j+1], o0[2*j+1]);
                *(float2*)&Xout[(k0    ) * XSTRIDE + 4 * rg + 2] = make_float2(o1[2*j],   o1[2*j]);
                *(float2*)&Xout[(k0 + 1) * XSTRIDE + 4 * rg + 2] = make_float2(o1[2*j+1], o1[2*j+1]);
            }
            __syncthreads();
            float* tmp = Xin; Xin = Xout; Xout = tmp;
        } else {
            float p0 = 0.f, p1 = 0.f;
            #pragma unroll
            for (int j = 0; j < 4; j++) {
                float2 w3v = *(const float2*)&W3[32 * j + cg * 2];
                p0 = fmaf(o0[2*j], w3v.x, fmaf(o0[2*j+1], w3v.y, p0));
                p1 = fmaf(o1[2*j], w3v.x, fmaf(o1[2*j+1], w3v.y, p1));
            }
            #pragma unroll
            for (int off = 8; off; off >>= 1) {
                p0 += __shfl_down_sync(0xffffffffu, p0, off, 16);
                p1 += __shfl_down_sync(0xffffffffu, p1, off, 16);
            }
            if (cg == 0) {
                float bb = b3[0];
                g_a0[r0 + rg * 2]     = p0 + bb;
                g_a0[r0 + rg * 2 + 1] = p1 + bb;
            }
        }
    }
}

// ---------------- edges: bitset build + hop-1 scatter (duplicates kept) -----
__global__ void edge_kernel(const void* __restrict__ ei, int ne) {
    int e = blockIdx.x * blockDim.x + threadIdx.x;
    if (e >= ne) return;
    int row, col;
    if (g_is64) {
        const long long* p = (const long long*)ei;
        row = (int)p[e];
        col = (int)p[ne + e];
    } else {
        const int* p = (const int*)ei;
        row = p[e];
        col = p[ne + e];
    }
    atomicOr(&g_A[row * NW + (col >> 5)], 1u << (col & 31));
    float v = 0.69314718055994531f * g_a0[col];
    long long q = __float2ll_rn(v * 4294967296.0f);
    atomicAdd((unsigned long long*)&g_stepq[row], (unsigned long long)q);
}

// ---------------- fused boolmm + gated matvec: 2 warps per row ---------------
// 256 threads = 8 warps; warp w -> row blockIdx.x*4 + (w>>1), half h = w&1.
// Each warp ORs all neighbors over its half-row (uint2 per lane = 64 bits),
// gathers its 64-float/lane segment from smem, then halves combine via smem.
__global__ __launch_bounds__(256)
void fused_hop_kernel(int phase, float* __restrict__ out_final) {
    const unsigned* M = phase ? g_A2 : g_A;

    const int tid  = threadIdx.x;
    const int wid  = tid >> 5;
    const int lane = tid & 31;
    const int r    = wid >> 1;          // row within block (0..3)
    const int h    = wid & 1;           // half (0..1)
    const int i    = blockIdx.x * 4 + r;

    __shared__ float          vsh[4096];
    __shared__ float          psum[256];
    __shared__ float          seg[64];
    __shared__ unsigned short list[8][WCAP];
    __shared__ float          part[8];

    // ---- stage the angle vector (+ per-64-float segment sums) ----
    {
        float s = 0.f;
        if (phase) {
            #pragma unroll
            for (int q = 0; q < 4; q++) {
                float4 v = *(const float4*)&g_av2[tid * 16 + q * 4];
                *(float4*)&vsh[tid * 16 + q * 4] = v;
                s += (v.x + v.y) + (v.z + v.w);
            }
        } else {
            #pragma unroll
            for (int q = 0; q < 16; q++) {
                int idx = tid * 16 + q;
                float v = g_a0[idx] + __ll2float_rn(g_stepq[idx]) * INV232;
                vsh[idx] = v;
                s += v;
            }
        }
        psum[tid] = s;
    }
    __syncthreads();
    if (tid < 64)
        seg[tid] = (psum[4 * tid] + psum[4 * tid + 1]) +
                   (psum[4 * tid + 2] + psum[4 * tid + 3]);

    // ---- build neighbor list for row i (each warp builds its own copy) ----
    uint4 aw = ((const uint4*)&g_A[i * NW])[lane];
    int nb = popc4(aw);
    int off = nb;
    #pragma unroll
    for (int d = 1; d < 32; d <<= 1) {
        int v = __shfl_up_sync(0xffffffffu, off, d);
        if (lane >= d) off += v;
    }
    const int total = __shfl_sync(0xffffffffu, off, 31);
    int pos = off - nb;
    unsigned short* L = list[wid];
    if (total <= WCAP) {
        unsigned mm; int jb;
        mm = aw.x; jb = lane * 128;
        while (mm) { int b = __ffs((int)mm) - 1; mm &= mm - 1; L[pos++] = (unsigned short)(jb + b); }
        mm = aw.y; jb = lane * 128 + 32;
        while (mm) { int b = __ffs((int)mm) - 1; mm &= mm - 1; L[pos++] = (unsigned short)(jb + b); }
        mm = aw.z; jb = lane * 128 + 64;
        while (mm) { int b = __ffs((int)mm) - 1; mm &= mm - 1; L[pos++] = (unsigned short)(jb + b); }
        mm = aw.w; jb = lane * 128 + 96;
        while (mm) { int b = __ffs((int)mm) - 1; mm &= mm - 1; L[pos++] = (unsigned short)(jb + b); }
    }
    __syncwarp();

    // wait for seg[] (written by tid<64) before any warp might use it
    __syncthreads();

    // ---- OR over neighbor rows (this warp's half: 64 words, uint2/lane) ----
    const int woff = h * 64 + 2 * lane;              // word offset in row
    unsigned ax = 0u, ay = 0u;
    if (total <= WCAP) {
        const int c = total;
        int j = 0;
        for (; j + 8 <= c; j += 8) {
            uint2 q0 = *(const uint2*)&M[(int)L[j]     * NW + woff];
            uint2 q1 = *(const uint2*)&M[(int)L[j + 1] * NW + woff];
            uint2 q2 = *(const uint2*)&M[(int)L[j + 2] * NW + woff];
            uint2 q3 = *(const uint2*)&M[(int)L[j + 3] * NW + woff];
            uint2 q4 = *(const uint2*)&M[(int)L[j + 4] * NW + woff];
            uint2 q5 = *(const uint2*)&M[(int)L[j + 5] * NW + woff];
            uint2 q6 = *(const uint2*)&M[(int)L[j + 6] * NW + woff];
            uint2 q7 = *(const uint2*)&M[(int)L[j + 7] * NW + woff];
            ax |= ((q0.x | q1.x) | (q2.x | q3.x)) | ((q4.x | q5.x) | (q6.x | q7.x));
            ay |= ((q0.y | q1.y) | (q2.y | q3.y)) | ((q4.y | q5.y) | (q6.y | q7.y));
        }
        for (; j < c; j++) {
            uint2 q = *(const uint2*)&M[(int)L[j] * NW + woff];
            ax |= q.x; ay |= q.y;
        }
    } else {
        // fallback: broadcast adjacency words and expand (pathological only)
        #pragma unroll
        for (int c4 = 0; c4 < 4; c4++) {
            unsigned mycomp = (c4 == 0) ? aw.x : (c4 == 1) ? aw.y : (c4 == 2) ? aw.z : aw.w;
            for (int src = 0; src < 32; src++) {
                unsigned mm = __shfl_sync(0xffffffffu, mycomp, src);
                int jb = src * 128 + c4 * 32;
                while (mm) {
                    int b = __ffs((int)mm) - 1; mm &= mm - 1;
                    uint2 q = *(const uint2*)&M[(jb + b) * NW + woff];
                    ax |= q.x; ay |= q.y;
                }
            }
        }
    }

    if (!phase) *(uint2*)&g_A2[i * NW + woff] = make_uint2(ax, ay);

    // ---- gated sum over this lane's 64-float segment ----
    const float* base = vsh + woff * 32;
    int pc = __popc(ax) + __popc(ay);
    float sv;
    if (pc > 32) {
        sv = seg[h * 32 + lane];
        unsigned m;
        m = ~ax; while (m) { int b = __ffs((int)m) - 1; m &= m - 1; sv -= base[b]; }
        m = ~ay; while (m) { int b = __ffs((int)m) - 1; m &= m - 1; sv -= base[32 + b]; }
    } else {
        sv = 0.f;
        unsigned m;
        m = ax; while (m) { int b = __ffs((int)m) - 1; m &= m - 1; sv += base[b]; }
        m = ay; while (m) { int b = __ffs((int)m) - 1; m &= m - 1; sv += base[32 + b]; }
    }
    #pragma unroll
    for (int o = 16; o; o >>= 1) sv += __shfl_down_sync(0xffffffffu, sv, o);
    if (lane == 0) part[wid] = sv;
    __syncthreads();

    // ---- combine halves + epilogue (threads 0..3 handle rows 0..3) ----
    if (tid < 4) {
        const int ii = blockIdx.x * 4 + tid;
        float tot = part[2 * tid] + part[2 * tid + 1];
        if (!phase) {
            float s1 = __ll2float_rn(g_stepq[ii]) * INV232;
            float ns = s1 + 1.0986122886681098f * tot;            // ln 3
            g_step[ii] = ns;
            g_av2[ii]  = vsh[ii] + ns;                             // a1 + step
        } else {
            out_final[ii] = vsh[ii] + g_step[ii] + 1.3862943611198906f * tot; // ln 4
        }
    }
}

// ---------------- launch ----------------------------------------------------
extern "C" void kernel_launch(void* const* d_in, const int* in_sizes, int n_in,
                              void* d_out, int out_size) {
    const float* coeffs = (const float*)d_in[0];
    const void*  ei     = d_in[1];
    const float* W0     = (const float*)d_in[2];
    const float* b0     = (const float*)d_in[3];
    const float* W1     = (const float*)d_in[4];
    const float* W2     = (const float*)d_in[5];
    const float* W3     = (const float*)d_in[6];
    const float* b3     = (const float*)d_in[7];
    float* out = (float*)d_out;

    const int ne = in_sizes[1] / 2;

    const int prep_blocks = (N * NW + 3 * 16384) / 256 + 1;
    prep_kernel<<<prep_blocks, 256>>>(W0, W1, W2, ei);

    mlp_kernel<<<N / MLP_R, 128>>>(coeffs, b0, W3, b3);

    edge_kernel<<<(ne + 255) / 256, 256>>>(ei, ne);

    fused_hop_kernel<<<N / 4, 256>>>(0, out);
    fused_hop_kernel<<<N / 4, 256>>>(1, out);
}

// round 7
// speedup vs baseline: 1.0072x; 1.0072x over previous
#include <cuda_runtime.h>
#include <math.h>

#define N      4096
#define D      128
#define NW     128          // 4096 bits / 32
#define MLP_R  16           // rows per MLP block
#define XSTRIDE 36          // dup-x smem row stride (floats)
#define INV232 2.3283064365386963e-10f   // 2^-32

// ---------------- scratch (device globals) ----------------------------------
__device__ unsigned  g_A  [N * NW];
__device__ unsigned  g_A2 [N * NW];
__device__ float     g_Wt [3 * D * D];   // pre-transposed weights, k-major
__device__ float     g_a0[N];
__device__ float     g_av2[N];
__device__ long long g_stepq[N];
__device__ float     g_step[N];
__device__ int       g_is64;

#define FMA2(acc, w, x) asm("fma.rn.f32x2 %0, %1, %2, %0;" : "+l"(acc) : "l"(w), "l"(x))
union U64F2 { unsigned long long u; float2 f; };

// ---------------- prep: zero A/stepq + transpose W0..W2 + dtype detect ------
__global__ void prep_kernel(const float* __restrict__ W0,
                            const float* __restrict__ W1,
                            const float* __restrict__ W2,
                            const void* __restrict__ ei) {
    if (blockIdx.x == gridDim.x - 1) {
        __shared__ int bad;
        if (threadIdx.x == 0) bad = 0;
        __syncthreads();
        const long long* p = (const long long*)ei;
        for (int i = threadIdx.x; i < 2048; i += blockDim.x) {
            long long v = p[i];
            if (v < 0 || v >= N) bad = 1;
        }
        __syncthreads();
        if (threadIdx.x == 0) g_is64 = bad ? 0 : 1;
        return;
    }
    int idx = blockIdx.x * 256 + threadIdx.x;
    if (idx < N * NW) {
        g_A[idx] = 0u;
        if (idx < N) g_stepq[idx] = 0ll;
    } else {
        int t = idx - N * NW;
        int m  = t >> 14;
        int tp = t & 16383;                  // tp = k*128 + c
        int c  = tp & 127;
        int k  = tp >> 7;
        const float* Ws = (m == 0) ? W0 : (m == 1 ? W1 : W2);
        g_Wt[m * 16384 + tp] = Ws[c * 128 + k];
    }
}

// ---------------- fused MLP: 3 x (GEMM+ReLU) + final dot, one kernel --------
__global__ __launch_bounds__(128, 4)
void mlp_kernel(const float* __restrict__ coeffs,
                const float* __restrict__ b0,
                const float* __restrict__ W3,
                const float* __restrict__ b3) {
    __shared__ float xa[128 * XSTRIDE];
    __shared__ float xb[128 * XSTRIDE];

    const int tid = threadIdx.x;
    const int r0  = blockIdx.x * MLP_R;
    const int rg  = tid >> 4;     // 8 row-groups of 2 rows
    const int cg  = tid & 15;     // 16 col-groups

    #pragma unroll
    for (int it = 0; it < 4; it++) {
        int idx = it * 128 + tid;
        int r  = idx >> 5;
        int kq = idx & 31;
        float4 v = *(const float4*)&coeffs[(r0 + r) * 128 + kq * 4];
        float vv[4] = {v.x, v.y, v.z, v.w};
        #pragma unroll
        for (int q = 0; q < 4; q++)
            *(float2*)&xa[(kq * 4 + q) * XSTRIDE + 2 * r] = make_float2(vv[q], vv[q]);
    }
    __syncthreads();

    float* Xin  = xa;
    float* Xout = xb;

    #pragma unroll
    for (int layer = 0; layer < 3; layer++) {
        const float* Wl = g_Wt + layer * 16384;

        unsigned long long a0p[4], a1p[4];
        #pragma unroll
        for (int j = 0; j < 4; j++) { a0p[j] = 0ull; a1p[j] = 0ull; }

        #pragma unroll 8
        for (int k = 0; k < 128; k++) {
            ulonglong2 xx = *(const ulonglong2*)&Xin[k * XSTRIDE + rg * 4];
            const float* wrow = Wl + k * 128 + cg * 2;
            unsigned long long w0 = *(const unsigned long long*)(wrow);
            unsigned long long w1 = *(const unsigned long long*)(wrow + 32);
            unsigned long long w2 = *(const unsigned long long*)(wrow + 64);
            unsigned long long w3 = *(const unsigned long long*)(wrow + 96);
            FMA2(a0p[0], w0, xx.x); FMA2(a1p[0], w0, xx.y);
            FMA2(a0p[1], w1, xx.x); FMA2(a1p[1], w1, xx.y);
            FMA2(a0p[2], w2, xx.x); FMA2(a1p[2], w2, xx.y);
            FMA2(a0p[3], w3, xx.x); FMA2(a1p[3], w3, xx.y);
        }

        float o0[8], o1[8];
        #pragma unroll
        for (int j = 0; j < 4; j++) {
            U64F2 u0, u1; u0.u = a0p[j]; u1.u = a1p[j];
            o0[2 * j] = u0.f.x; o0[2 * j + 1] = u0.f.y;
            o1[2 * j] = u1.f.x; o1[2 * j + 1] = u1.f.y;
        }
        if (layer == 0) {
            #pragma unroll
            for (int j = 0; j < 4; j++) {
                float2 bb = *(const float2*)&b0[32 * j + cg * 2];
                o0[2 * j] += bb.x; o0[2 * j + 1] += bb.y;
                o1[2 * j] += bb.x; o1[2 * j + 1] += bb.y;
            }
        }
        #pragma unroll
        for (int j = 0; j < 8; j++) {
            o0[j] = fmaxf(o0[j], 0.f);
            o1[j] = fmaxf(o1[j], 0.f);
        }

        if (layer < 2) {
            #pragma unroll
            for (int j = 0; j < 4; j++) {
                int k0 = cg * 2 + 32 * j;
                *(float2*)&Xout[(k0    ) * XSTRIDE + 4 * rg    ] = make_float2(o0[2*j],   o0[2*j]);
                *(float2*)&Xout[(k0 + 1) * XSTRIDE + 4 * rg    ] = make_float2(o0[2*j+1], o0[2*j+1]);
                *(float2*)&Xout[(k0    ) * XSTRIDE + 4 * rg + 2] = make_float2(o1[2*j],   o1[2*j]);
                *(float2*)&Xout[(k0 + 1) * XSTRIDE + 4 * rg + 2] = make_float2(o1[2*j+1], o1[2*j+1]);
            }
            __syncthreads();
            float* tmp = Xin; Xin = Xout; Xout = tmp;
        } else {
            float p0 = 0.f, p1 = 0.f;
            #pragma unroll
            for (int j = 0; j < 4; j++) {
                float2 w3v = *(const float2*)&W3[32 * j + cg * 2];
                p0 = fmaf(o0[2*j], w3v.x, fmaf(o0[2*j+1], w3v.y, p0));
                p1 = fmaf(o1[2*j], w3v.x, fmaf(o1[2*j+1], w3v.y, p1));
            }
            #pragma unroll
            for (int off = 8; off; off >>= 1) {
                p0 += __shfl_down_sync(0xffffffffu, p0, off, 16);
                p1 += __shfl_down_sync(0xffffffffu, p1, off, 16);
            }
            if (cg == 0) {
                float bb = b3[0];
                g_a0[r0 + rg * 2]     = p0 + bb;
                g_a0[r0 + rg * 2 + 1] = p1 + bb;
            }
        }
    }
}

// ---------------- edges: bitset build + hop-1 scatter (duplicates kept) -----
__global__ void edge_kernel(const void* __restrict__ ei, int ne) {
    int e = blockIdx.x * blockDim.x + threadIdx.x;
    if (e >= ne) return;
    int row, col;
    if (g_is64) {
        const long long* p = (const long long*)ei;
        row = (int)p[e];
        col = (int)p[ne + e];
    } else {
        const int* p = (const int*)ei;
        row = p[e];
        col = p[ne + e];
    }
    atomicOr(&g_A[row * NW + (col >> 5)], 1u << (col & 31));
    float v = 0.69314718055994531f * g_a0[col];
    long long q = __float2ll_rn(v * 4294967296.0f);
    atomicAdd((unsigned long long*)&g_stepq[row], (unsigned long long)q);
}

// ---------------- fused boolmm + gated matvec: listless, warp-uniform --------
// 512 threads = 16 warps; warp pair (2r,2r+1) -> row blockIdx.x*8 + r; each
// warp owns half the row's columns (uint2/lane). Neighbor indices come from
// warp-UNIFORM LDG.128 reads of the adjacency row (broadcast, L1-hit) and a
// warp-uniform bit loop — no smem list, no divergence, no scan.
__global__ __launch_bounds__(512)
void fused_hop_kernel(int phase, float* __restrict__ out_final) {
    const unsigned* M = phase ? g_A2 : g_A;

    const int tid  = threadIdx.x;
    const int wid  = tid >> 5;
    const int lane = tid & 31;
    const int r    = wid >> 1;          // row within block (0..7)
    const int h    = wid & 1;           // column half (0..1)
    const int i    = blockIdx.x * 8 + r;

    __shared__ float vsh[4096];
    __shared__ float psum[512];
    __shared__ float seg[64];
    __shared__ float part[16];

    // ---- stage the angle vector (8 floats/thread) + per-64 segment sums ----
    {
        float s = 0.f;
        if (phase) {
            #pragma unroll
            for (int q = 0; q < 2; q++) {
                float4 v = *(const float4*)&g_av2[tid * 8 + q * 4];
                *(float4*)&vsh[tid * 8 + q * 4] = v;
                s += (v.x + v.y) + (v.z + v.w);
            }
        } else {
            #pragma unroll
            for (int q = 0; q < 8; q++) {
                int idx = tid * 8 + q;
                float v = g_a0[idx] + __ll2float_rn(g_stepq[idx]) * INV232;
                vsh[idx] = v;
                s += v;
            }
        }
        psum[tid] = s;
    }
    __syncthreads();
    if (tid < 64) {
        float s = 0.f;
        #pragma unroll
        for (int q = 0; q < 8; q++) s += psum[tid * 8 + q];
        seg[tid] = s;
    }
    __syncthreads();

    // ---- OR over neighbor rows: warp-uniform neighbor iteration ------------
    const int woff = h * 64 + 2 * lane;              // this lane's word pair
    const uint4* Arow = (const uint4*)&g_A[i * NW];
    unsigned ax = 0u, ay = 0u;

    #pragma unroll 4
    for (int c = 0; c < 32; c++) {
        uint4 mw = __ldg(&Arow[c]);                  // uniform address: 1 wf
        int jb = c * 128;
        unsigned m;
        m = mw.x;
        while (m) {
            int b = __ffs((int)m) - 1; m &= m - 1;
            uint2 q = *(const uint2*)&M[(jb + b) * NW + woff];
            ax |= q.x; ay |= q.y;
        }
        m = mw.y;
        while (m) {
            int b = __ffs((int)m) - 1; m &= m - 1;
            uint2 q = *(const uint2*)&M[(jb + 32 + b) * NW + woff];
            ax |= q.x; ay |= q.y;
        }
        m = mw.z;
        while (m) {
            int b = __ffs((int)m) - 1; m &= m - 1;
            uint2 q = *(const uint2*)&M[(jb + 64 + b) * NW + woff];
            ax |= q.x; ay |= q.y;
        }
        m = mw.w;
        while (m) {
            int b = __ffs((int)m) - 1; m &= m - 1;
            uint2 q = *(const uint2*)&M[(jb + 96 + b) * NW + woff];
            ax |= q.x; ay |= q.y;
        }
    }

    if (!phase) *(uint2*)&g_A2[i * NW + woff] = make_uint2(ax, ay);

    // ---- gated sum over this lane's 64-float segment (complement trick) ----
    const float* base = vsh + woff * 32;
    int pc = __popc(ax) + __popc(ay);
    float sv;
    if (pc > 32) {
        sv = seg[h * 32 + lane];
        unsigned m;
        m = ~ax; while (m) { int b = __ffs((int)m) - 1; m &= m - 1; sv -= base[b]; }
        m = ~ay; while (m) { int b = __ffs((int)m) - 1; m &= m - 1; sv -= base[32 + b]; }
    } else {
        sv = 0.f;
        unsigned m;
        m = ax; while (m) { int b = __ffs((int)m) - 1; m &= m - 1; sv += base[b]; }
        m = ay; while (m) { int b = __ffs((int)m) - 1; m &= m - 1; sv += base[32 + b]; }
    }
    #pragma unroll
    for (int o = 16; o; o >>= 1) sv += __shfl_down_sync(0xffffffffu, sv, o);
    if (lane == 0) part[wid] = sv;
    __syncthreads();

    // ---- combine halves + epilogue (threads 0..7 handle rows 0..7) ---------
    if (tid < 8) {
        const int ii = blockIdx.x * 8 + tid;
        float tot = part[2 * tid] + part[2 * tid + 1];
        if (!phase) {
            float s1 = __ll2float_rn(g_stepq[ii]) * INV232;
            float ns = s1 + 1.0986122886681098f * tot;            // ln 3
            g_step[ii] = ns;
            g_av2[ii]  = vsh[ii] + ns;                             // a1 + step
        } else {
            out_final[ii] = vsh[ii] + g_step[ii] + 1.3862943611198906f * tot; // ln 4
        }
    }
}

// ---------------- launch ----------------------------------------------------
extern "C" void kernel_launch(void* const* d_in, const int* in_sizes, int n_in,
                              void* d_out, int out_size) {
    const float* coeffs = (const float*)d_in[0];
    const void*  ei     = d_in[1];
    const float* W0     = (const float*)d_in[2];
    const float* b0     = (const float*)d_in[3];
    const float* W1     = (const float*)d_in[4];
    const float* W2     = (const float*)d_in[5];
    const float* W3     = (const float*)d_in[6];
    const float* b3     = (const float*)d_in[7];
    float* out = (float*)d_out;

    const int ne = in_sizes[1] / 2;

    const int prep_blocks = (N * NW + 3 * 16384) / 256 + 1;
    prep_kernel<<<prep_blocks, 256>>>(W0, W1, W2, ei);

    mlp_kernel<<<N / MLP_R, 128>>>(coeffs, b0, W3, b3);

    edge_kernel<<<(ne + 255) / 256, 256>>>(ei, ne);

    fused_hop_kernel<<<N / 8, 512>>>(0, out);
    fused_hop_kernel<<<N / 8, 512>>>(1, out);
}

// round 8
// speedup vs baseline: 1.3011x; 1.2918x over previous
#include <cuda_runtime.h>
#include <math.h>

#define N      4096
#define D      128
#define NW     128          // 4096 bits / 32
#define MLP_R  16           // rows per MLP block
#define XSTRIDE 36          // dup-x smem row stride (floats)
#define CAP    192          // per-row unique-neighbor list capacity
#define INV232 2.3283064365386963e-10f   // 2^-32

// ---------------- scratch (device globals) ----------------------------------
__device__ unsigned       g_A  [N * NW];
__device__ unsigned       g_A2 [N * NW];
__device__ unsigned short g_nbr[N * CAP];   // unique neighbor lists
__device__ int            g_cnt[N];
__device__ float          g_Wt [3 * D * D]; // pre-transposed weights, k-major
__device__ float          g_a0[N];
__device__ float          g_a1[N];
__device__ float          g_av2[N];
__device__ long long      g_stepq[N];
__device__ float          g_step[N];
__device__ int            g_is64;

#define FMA2(acc, w, x) asm("fma.rn.f32x2 %0, %1, %2, %0;" : "+l"(acc) : "l"(w), "l"(x))
union U64F2 { unsigned long long u; float2 f; };

// ---------------- prep: zero A/cnt/stepq + transpose W + dtype detect -------
__global__ void prep_kernel(const float* __restrict__ W0,
                            const float* __restrict__ W1,
                            const float* __restrict__ W2,
                            const void* __restrict__ ei) {
    if (blockIdx.x == gridDim.x - 1) {
        __shared__ int bad;
        if (threadIdx.x == 0) bad = 0;
        __syncthreads();
        const long long* p = (const long long*)ei;
        for (int i = threadIdx.x; i < 2048; i += blockDim.x) {
            long long v = p[i];
            if (v < 0 || v >= N) bad = 1;
        }
        __syncthreads();
        if (threadIdx.x == 0) g_is64 = bad ? 0 : 1;
        return;
    }
    int idx = blockIdx.x * 256 + threadIdx.x;
    if (idx < N * NW) {
        g_A[idx] = 0u;
        if (idx < N) { g_stepq[idx] = 0ll; g_cnt[idx] = 0; }
    } else {
        int t = idx - N * NW;
        int m  = t >> 14;
        int tp = t & 16383;                  // tp = k*128 + c
        int c  = tp & 127;
        int k  = tp >> 7;
        const float* Ws = (m == 0) ? W0 : (m == 1 ? W1 : W2);
        g_Wt[m * 16384 + tp] = Ws[c * 128 + k];
    }
}

// ---------------- fused MLP: 3 x (GEMM+ReLU) + final dot, one kernel --------
__global__ __launch_bounds__(128, 4)
void mlp_kernel(const float* __restrict__ coeffs,
                const float* __restrict__ b0,
                const float* __restrict__ W3,
                const float* __restrict__ b3) {
    __shared__ float xa[128 * XSTRIDE];
    __shared__ float xb[128 * XSTRIDE];

    const int tid = threadIdx.x;
    const int r0  = blockIdx.x * MLP_R;
    const int rg  = tid >> 4;     // 8 row-groups of 2 rows
    const int cg  = tid & 15;     // 16 col-groups

    #pragma unroll
    for (int it = 0; it < 4; it++) {
        int idx = it * 128 + tid;
        int r  = idx >> 5;
        int kq = idx & 31;
        float4 v = *(const float4*)&coeffs[(r0 + r) * 128 + kq * 4];
        float vv[4] = {v.x, v.y, v.z, v.w};
        #pragma unroll
        for (int q = 0; q < 4; q++)
            *(float2*)&xa[(kq * 4 + q) * XSTRIDE + 2 * r] = make_float2(vv[q], vv[q]);
    }
    __syncthreads();

    float* Xin  = xa;
    float* Xout = xb;

    #pragma unroll
    for (int layer = 0; layer < 3; layer++) {
        const float* Wl = g_Wt + layer * 16384;

        unsigned long long a0p[4], a1p[4];
        #pragma unroll
        for (int j = 0; j < 4; j++) { a0p[j] = 0ull; a1p[j] = 0ull; }

        #pragma unroll 8
        for (int k = 0; k < 128; k++) {
            ulonglong2 xx = *(const ulonglong2*)&Xin[k * XSTRIDE + rg * 4];
            const float* wrow = Wl + k * 128 + cg * 2;
            unsigned long long w0 = *(const unsigned long long*)(wrow);
            unsigned long long w1 = *(const unsigned long long*)(wrow + 32);
            unsigned long long w2 = *(const unsigned long long*)(wrow + 64);
            unsigned long long w3 = *(const unsigned long long*)(wrow + 96);
            FMA2(a0p[0], w0, xx.x); FMA2(a1p[0], w0, xx.y);
            FMA2(a0p[1], w1, xx.x); FMA2(a1p[1], w1, xx.y);
            FMA2(a0p[2], w2, xx.x); FMA2(a1p[2], w2, xx.y);
            FMA2(a0p[3], w3, xx.x); FMA2(a1p[3], w3, xx.y);
        }

        float o0[8], o1[8];
        #pragma unroll
        for (int j = 0; j < 4; j++) {
            U64F2 u0, u1; u0.u = a0p[j]; u1.u = a1p[j];
            o0[2 * j] = u0.f.x; o0[2 * j + 1] = u0.f.y;
            o1[2 * j] = u1.f.x; o1[2 * j + 1] = u1.f.y;
        }
        if (layer == 0) {
            #pragma unroll
            for (int j = 0; j < 4; j++) {
                float2 bb = *(const float2*)&b0[32 * j + cg * 2];
                o0[2 * j] += bb.x; o0[2 * j + 1] += bb.y;
                o1[2 * j] += bb.x; o1[2 * j + 1] += bb.y;
            }
        }
        #pragma unroll
        for (int j = 0; j < 8; j++) {
            o0[j] = fmaxf(o0[j], 0.f);
            o1[j] = fmaxf(o1[j], 0.f);
        }

        if (layer < 2) {
            #pragma unroll
            for (int j = 0; j < 4; j++) {
                int k0 = cg * 2 + 32 * j;
                *(float2*)&Xout[(k0    ) * XSTRIDE + 4 * rg    ] = make_float2(o0[2*j],   o0[2*j]);
                *(float2*)&Xout[(k0 + 1) * XSTRIDE + 4 * rg    ] = make_float2(o0[2*j+1], o0[2*j+1]);
                *(float2*)&Xout[(k0    ) * XSTRIDE + 4 * rg + 2] = make_float2(o1[2*j],   o1[2*j]);
                *(float2*)&Xout[(k0 + 1) * XSTRIDE + 4 * rg + 2] = make_float2(o1[2*j+1], o1[2*j+1]);
            }
            __syncthreads();
            float* tmp = Xin; Xin = Xout; Xout = tmp;
        } else {
            float p0 = 0.f, p1 = 0.f;
            #pragma unroll
            for (int j = 0; j < 4; j++) {
                float2 w3v = *(const float2*)&W3[32 * j + cg * 2];
                p0 = fmaf(o0[2*j], w3v.x, fmaf(o0[2*j+1], w3v.y, p0));
                p1 = fmaf(o1[2*j], w3v.x, fmaf(o1[2*j+1], w3v.y, p1));
            }
            #pragma unroll
            for (int off = 8; off; off >>= 1) {
                p0 += __shfl_down_sync(0xffffffffu, p0, off, 16);
                p1 += __shfl_down_sync(0xffffffffu, p1, off, 16);
            }
            if (cg == 0) {
                float bb = b3[0];
                g_a0[r0 + rg * 2]     = p0 + bb;
                g_a0[r0 + rg * 2 + 1] = p1 + bb;
            }
        }
    }
}

// ---------------- edges: bitset + UNIQUE neighbor list + hop-1 scatter ------
__global__ void edge_kernel(const void* __restrict__ ei, int ne) {
    int e = blockIdx.x * blockDim.x + threadIdx.x;
    if (e >= ne) return;
    int row, col;
    if (g_is64) {
        const long long* p = (const long long*)ei;
        row = (int)p[e];
        col = (int)p[ne + e];
    } else {
        const int* p = (const int*)ei;
        row = p[e];
        col = p[ne + e];
    }
    unsigned bit = 1u << (col & 31);
    unsigned old = atomicOr(&g_A[row * NW + (col >> 5)], bit);
    if (!(old & bit)) {                       // first time this (row,col) bit set
        int p = atomicAdd(&g_cnt[row], 1);
        if (p < CAP) g_nbr[row * CAP + p] = (unsigned short)col;
    }
    float v = 0.69314718055994531f * g_a0[col];
    long long q = __float2ll_rn(v * 4294967296.0f);
    atomicAdd((unsigned long long*)&g_stepq[row], (unsigned long long)q);
}

// ---------------- a1 = a0 + step1 --------------------------------------------
__global__ void a1_kernel() {
    int i = blockIdx.x * blockDim.x + threadIdx.x;
    if (i < N) g_a1[i] = g_a0[i] + __ll2float_rn(g_stepq[i]) * INV232;
}

// ---------------- fused boolmm + gated matvec: neighbor-list driven ----------
// 512 threads = 16 warps; warps (2r,2r+1) -> row blockIdx.x*8+r, halves h=0/1.
// OR loop reads the unique neighbor list (uniform) -> 8 independent LDG.64
// per iteration, fully pipelined. No bit decode in the hot path.
__global__ __launch_bounds__(512)
void fused_hop_kernel(int phase, float* __restrict__ out_final) {
    const unsigned* M   = phase ? g_A2 : g_A;
    const float*    vec = phase ? g_av2 : g_a1;

    const int tid  = threadIdx.x;
    const int wid  = tid >> 5;
    const int lane = tid & 31;
    const int r    = wid >> 1;          // row within block (0..7)
    const int h    = wid & 1;           // column half (0..1)
    const int i    = blockIdx.x * 8 + r;

    __shared__ float vsh[4096];
    __shared__ float psum[512];
    __shared__ float seg[64];
    __shared__ float part[16];

    // ---- stage the angle vector (8 floats/thread) + per-64 segment sums ----
    {
        float s = 0.f;
        #pragma unroll
        for (int q = 0; q < 2; q++) {
            float4 v = *(const float4*)&vec[tid * 8 + q * 4];
            *(float4*)&vsh[tid * 8 + q * 4] = v;
            s += (v.x + v.y) + (v.z + v.w);
        }
        psum[tid] = s;
    }
    __syncthreads();
    if (tid < 64) {
        float s = 0.f;
        #pragma unroll
        for (int q = 0; q < 8; q++) s += psum[tid * 8 + q];
        seg[tid] = s;
    }
    __syncthreads();

    // ---- OR over neighbor rows via unique neighbor list ---------------------
    const int woff = h * 64 + 2 * lane;              // this lane's word pair
    const int cnt  = g_cnt[i];
    unsigned ax = 0u, ay = 0u;

    if (cnt <= CAP) {
        const unsigned short* nb = g_nbr + i * CAP;
        int j = 0;
        for (; j + 8 <= cnt; j += 8) {
            uint4 nn = *(const uint4*)&nb[j];        // 8 ushorts, uniform
            int n0 = nn.x & 0xffff, n1 = nn.x >> 16;
            int n2 = nn.y & 0xffff, n3 = nn.y >> 16;
            int n4 = nn.z & 0xffff, n5 = nn.z >> 16;
            int n6 = nn.w & 0xffff, n7 = nn.w >> 16;
            uint2 q0 = __ldg((const uint2*)&M[n0 * NW + woff]);
            uint2 q1 = __ldg((const uint2*)&M[n1 * NW + woff]);
            uint2 q2 = __ldg((const uint2*)&M[n2 * NW + woff]);
            uint2 q3 = __ldg((const uint2*)&M[n3 * NW + woff]);
            uint2 q4 = __ldg((const uint2*)&M[n4 * NW + woff]);
            uint2 q5 = __ldg((const uint2*)&M[n5 * NW + woff]);
            uint2 q6 = __ldg((const uint2*)&M[n6 * NW + woff]);
            uint2 q7 = __ldg((const uint2*)&M[n7 * NW + woff]);
            ax |= ((q0.x | q1.x) | (q2.x | q3.x)) | ((q4.x | q5.x) | (q6.x | q7.x));
            ay |= ((q0.y | q1.y) | (q2.y | q3.y)) | ((q4.y | q5.y) | (q6.y | q7.y));
        }
        for (; j < cnt; j++) {
            int n = nb[j];
            uint2 q = __ldg((const uint2*)&M[n * NW + woff]);
            ax |= q.x; ay |= q.y;
        }
    } else {
        // fallback: bit-walk over the adjacency row (pathological degrees)
        const uint4* Arow = (const uint4*)&g_A[i * NW];
        for (int c = 0; c < 32; c++) {
            uint4 mw = __ldg(&Arow[c]);
            int jb = c * 128;
            unsigned m;
            m = mw.x; while (m) { int b = __ffs((int)m) - 1; m &= m - 1;
                uint2 q = *(const uint2*)&M[(jb + b) * NW + woff]; ax |= q.x; ay |= q.y; }
            m = mw.y; while (m) { int b = __ffs((int)m) - 1; m &= m - 1;
                uint2 q = *(const uint2*)&M[(jb + 32 + b) * NW + woff]; ax |= q.x; ay |= q.y; }
            m = mw.z; while (m) { int b = __ffs((int)m) - 1; m &= m - 1;
                uint2 q = *(const uint2*)&M[(jb + 64 + b) * NW + woff]; ax |= q.x; ay |= q.y; }
            m = mw.w; while (m) { int b = __ffs((int)m) - 1; m &= m - 1;
                uint2 q = *(const uint2*)&M[(jb + 96 + b) * NW + woff]; ax |= q.x; ay |= q.y; }
        }
    }

    if (!phase) *(uint2*)&g_A2[i * NW + woff] = make_uint2(ax, ay);

    // ---- gated sum over this lane's 64-float segment (complement trick) ----
    const float* base = vsh + woff * 32;
    int pc = __popc(ax) + __popc(ay);
    float sv;
    if (pc > 32) {
        sv = seg[h * 32 + lane];
        unsigned m;
        m = ~ax; while (m) { int b = __ffs((int)m) - 1; m &= m - 1; sv -= base[b]; }
        m = ~ay; while (m) { int b = __ffs((int)m) - 1; m &= m - 1; sv -= base[32 + b]; }
    } else {
        sv = 0.f;
        unsigned m;
        m = ax; while (m) { int b = __ffs((int)m) - 1; m &= m - 1; sv += base[b]; }
        m = ay; while (m) { int b = __ffs((int)m) - 1; m &= m - 1; sv += base[32 + b]; }
    }
    #pragma unroll
    for (int o = 16; o; o >>= 1) sv += __shfl_down_sync(0xffffffffu, sv, o);
    if (lane == 0) part[wid] = sv;
    __syncthreads();

    // ---- combine halves + epilogue (threads 0..7 handle rows 0..7) ---------
    if (tid < 8) {
        const int ii = blockIdx.x * 8 + tid;
        float tot = part[2 * tid] + part[2 * tid + 1];
        if (!phase) {
            float s1 = __ll2float_rn(g_stepq[ii]) * INV232;
            float ns = s1 + 1.0986122886681098f * tot;            // ln 3
            g_step[ii] = ns;
            g_av2[ii]  = vsh[ii] + ns;                             // a1 + step
        } else {
            out_final[ii] = vsh[ii] + g_step[ii] + 1.3862943611198906f * tot; // ln 4
        }
    }
}

// ---------------- launch ----------------------------------------------------
extern "C" void kernel_launch(void* const* d_in, const int* in_sizes, int n_in,
                              void* d_out, int out_size) {
    const float* coeffs = (const float*)d_in[0];
    const void*  ei     = d_in[1];
    const float* W0     = (const float*)d_in[2];
    const float* b0     = (const float*)d_in[3];
    const float* W1     = (const float*)d_in[4];
    const float* W2     = (const float*)d_in[5];
    const float* W3     = (const float*)d_in[6];
    const float* b3     = (const float*)d_in[7];
    float* out = (float*)d_out;

    const int ne = in_sizes[1] / 2;

    const int prep_blocks = (N * NW + 3 * 16384) / 256 + 1;
    prep_kernel<<<prep_blocks, 256>>>(W0, W1, W2, ei);

    mlp_kernel<<<N / MLP_R, 128>>>(coeffs, b0, W3, b3);

    edge_kernel<<<(ne + 255) / 256, 256>>>(ei, ne);
    a1_kernel<<<N / 256, 256>>>();

    fused_hop_kernel<<<N / 8, 512>>>(0, out);
    fused_hop_kernel<<<N / 8, 512>>>(1, out);
}